// round 16
// baseline (speedup 1.0000x reference)
#include <cuda_runtime.h>
#include <cuda_fp16.h>
#include <cstdint>

// ---------------- problem dims ----------------
#define M_DIM 4096
#define N_DIM 1024
#define E_DIM 16
#define I_DIM 1024
#define K_DIM 16384

// ---------------- GEMM config -----------------
#define BM 128
#define BN 128
#define BK 64
#define STAGES 3
#define NTHREADS 256
#define KCHUNKS 8            // split-K: 2048 CTAs, uniform 32 iters each
#define NT_ITERS 32
#define NTILES ((M_DIM / BM) * (N_DIM / BN))     // 256 output tiles

// smem: 3 stages of (A 16KB + B 16KB), mbarriers, relu flag
#define A_OFF 0
#define B_OFF 16384
#define STAGE_BYTES 32768
#define BAR_BASE (STAGES * STAGE_BYTES)
#define FULL_OFF(s)  (BAR_BASE + (s) * 8)
#define EMPTY_OFF(s) (BAR_BASE + 24 + (s) * 8)
#define FLAG_OFF     (BAR_BASE + 48)
#define SMEM_TOTAL (BAR_BASE + 64)               // 98368 -> 2 CTAs/SM

// ---------------- device scratch --------------
__device__ __align__(1024) __half g_A [(size_t)M_DIM * K_DIM]; // 128 MiB: cw*x fp16
__device__ __align__(1024) __half g_Wt[(size_t)N_DIM * K_DIM]; // 32 MiB:  W^T [n][k]
__device__ int g_cnt[NTILES];                                  // per-tile arrival counters

// ---------------- prep kernels ----------------
__global__ void prep_w_kernel(const float* __restrict__ W) {
    __shared__ float t[32][33];
    const int k0 = blockIdx.x * 32, o0 = blockIdx.y * 32;
    const int tx = threadIdx.x, ty = threadIdx.y;  // 32 x 8
#pragma unroll
    for (int i = 0; i < 4; ++i)
        t[ty + i * 8][tx] = W[(size_t)(k0 + ty + i * 8) * N_DIM + o0 + tx];
    __syncthreads();
#pragma unroll
    for (int i = 0; i < 4; ++i) {
        float v = t[tx][ty + i * 8];
        g_Wt[(size_t)(o0 + ty + i * 8) * K_DIM + k0 + tx] = __float2half_rn(v);
    }
}

__global__ void prep_a_kernel(const float* __restrict__ x,
                              const float* __restrict__ cw) {
    size_t idx    = (size_t)blockIdx.x * blockDim.x + threadIdx.x;
    size_t stride = (size_t)gridDim.x * blockDim.x;
    const size_t total = (size_t)M_DIM * (I_DIM / 4);
    for (; idx < total; idx += stride) {
        size_t b  = idx >> 8;
        int    i4 = (int)(idx & 255) * 4;
        float4 xv = *reinterpret_cast<const float4*>(x + (b << 10) + i4);
        const float4 c0 = *reinterpret_cast<const float4*>(cw + b * E_DIM);
        const float4 c1 = *reinterpret_cast<const float4*>(cw + b * E_DIM + 4);
        const float4 c2 = *reinterpret_cast<const float4*>(cw + b * E_DIM + 8);
        const float4 c3 = *reinterpret_cast<const float4*>(cw + b * E_DIM + 12);
        float cs[16] = {c0.x, c0.y, c0.z, c0.w, c1.x, c1.y, c1.z, c1.w,
                        c2.x, c2.y, c2.z, c2.w, c3.x, c3.y, c3.z, c3.w};
        __half* dst = g_A + b * (size_t)K_DIM + i4;
#pragma unroll
        for (int e = 0; e < E_DIM; ++e) {
            float c = cs[e];
            __half2 h0 = __floats2half2_rn(c * xv.x, c * xv.y);
            __half2 h1 = __floats2half2_rn(c * xv.z, c * xv.w);
            uint2 o;
            o.x = *reinterpret_cast<uint32_t*>(&h0);
            o.y = *reinterpret_cast<uint32_t*>(&h1);
            *reinterpret_cast<uint2*>(dst + e * I_DIM) = o;
        }
    }
}

// out = cw @ bias (partials accumulate on top); also reset tile counters
__global__ void init_out_kernel(float* __restrict__ out,
                                const float* __restrict__ cw,
                                const float* __restrict__ bias) {
    size_t idx = (size_t)blockIdx.x * blockDim.x + threadIdx.x;
    if (idx < NTILES) g_cnt[idx] = 0;
    const size_t n4 = (size_t)M_DIM * N_DIM / 4;
    if (idx >= n4) return;
    size_t b = idx >> 8;
    int    o = (int)(idx & 255) * 4;
    float4 acc = make_float4(0.f, 0.f, 0.f, 0.f);
#pragma unroll
    for (int e = 0; e < E_DIM; ++e) {
        float c = cw[b * E_DIM + e];
        float4 bz = *reinterpret_cast<const float4*>(bias + (size_t)e * N_DIM + o);
        acc.x += c * bz.x; acc.y += c * bz.y;
        acc.z += c * bz.z; acc.w += c * bz.w;
    }
    *reinterpret_cast<float4*>(out + b * N_DIM + o) = acc;
}

// ---------------- asm helpers ----------------
__device__ __forceinline__ void cp_async16(uint32_t s, const void* g) {
    asm volatile("cp.async.cg.shared.global [%0], [%1], 16;\n" :: "r"(s), "l"(g));
}
__device__ __forceinline__ void cpasync_arrive_noinc(uint32_t mbar) {
    asm volatile("cp.async.mbarrier.arrive.noinc.shared::cta.b64 [%0];" :: "r"(mbar) : "memory");
}
__device__ __forceinline__ void mbar_init(uint32_t a, uint32_t cnt) {
    asm volatile("mbarrier.init.shared.b64 [%0], %1;" :: "r"(a), "r"(cnt) : "memory");
}
__device__ __forceinline__ void mbar_arrive(uint32_t a) {
    asm volatile("mbarrier.arrive.shared.b64 _, [%0];" :: "r"(a) : "memory");
}
__device__ __forceinline__ void wait_parity(uint32_t mbar, uint32_t ph) {
    asm volatile("{\n\t.reg .pred P;\nWL%=:\n\t"
                 "mbarrier.try_wait.parity.acquire.cta.shared::cta.b64 P, [%0], %1, 0x989680;\n\t"
                 "@!P bra WL%=;\n\t}"
                 :: "r"(mbar), "r"(ph) : "memory");
}
__device__ __forceinline__ void ldsm_x4(uint32_t* r, uint32_t addr) {
    asm volatile("ldmatrix.sync.aligned.m8n8.x4.shared.b16 {%0,%1,%2,%3}, [%4];"
                 : "=r"(r[0]), "=r"(r[1]), "=r"(r[2]), "=r"(r[3]) : "r"(addr));
}
__device__ __forceinline__ void mma_f16(float* c, const uint32_t* a, const uint32_t* b) {
    asm volatile(
        "mma.sync.aligned.m16n8k16.row.col.f32.f16.f16.f32 "
        "{%0,%1,%2,%3}, {%4,%5,%6,%7}, {%8,%9}, {%0,%1,%2,%3};"
        : "+f"(c[0]), "+f"(c[1]), "+f"(c[2]), "+f"(c[3])
        : "r"(a[0]), "r"(a[1]), "r"(a[2]), "r"(a[3]), "r"(b[0]), "r"(b[1]));
}
__device__ __forceinline__ void red_add_v2(float* p, float a, float b) {
    asm volatile("red.global.add.v2.f32 [%0], {%1, %2};"
                 :: "l"(p), "f"(a), "f"(b) : "memory");
}

// ---------------- tile loader ----------------
__device__ __forceinline__ void issue_stage(uint32_t st,
                                            const __half* pA, const __half* pB,
                                            uint32_t dst0) {
#pragma unroll
    for (int p = 0; p < 4; ++p)
        cp_async16(st + A_OFF + dst0 + p * (32 * 128), pA + (size_t)p * 32 * K_DIM);
#pragma unroll
    for (int p = 0; p < 4; ++p)
        cp_async16(st + B_OFF + dst0 + p * (32 * 128), pB + (size_t)p * 32 * K_DIM);
}

// ---------------- fragment loads (verified mapping) ----------------
__device__ __forceinline__ void load_frags(uint32_t st, int s,
                                           int wm, int wn, int lane,
                                           uint32_t a[4][4], uint32_t b[4][2]) {
    const int r16 = lane & 15;
    const int hh  = lane >> 4;
#pragma unroll
    for (int mt = 0; mt < 4; ++mt) {
        int row = wm * 64 + mt * 16 + r16;
        int ch  = s * 2 + hh;
        ldsm_x4(a[mt], st + A_OFF + (uint32_t)(row * 128 + ((ch ^ (row & 7)) << 4)));
    }
    const int m  = lane >> 3;
    const int rr = lane & 7;
    {
        int n  = wn * 32 + ((m >> 1) << 3) + rr;
        int ch = s * 2 + (m & 1);
        uint32_t t[4];
        ldsm_x4(t, st + B_OFF + (uint32_t)(n * 128 + ((ch ^ (n & 7)) << 4)));
        b[0][0] = t[0]; b[0][1] = t[1];
        b[1][0] = t[2]; b[1][1] = t[3];
        int n2 = n + 16;
        ldsm_x4(t, st + B_OFF + (uint32_t)(n2 * 128 + ((ch ^ (n2 & 7)) << 4)));
        b[2][0] = t[0]; b[2][1] = t[1];
        b[3][0] = t[2]; b[3][1] = t[3];
    }
}

// ---------------- main GEMM (R15 core + fused ReLU via arrival counter) ------
__global__ void __launch_bounds__(NTHREADS, 2)
gemm_kernel(float* __restrict__ out) {
    extern __shared__ char smem_raw[];
    const uint32_t smem_base = (uint32_t)__cvta_generic_to_shared(smem_raw);
    const int tid  = threadIdx.x;
    const int lane = tid & 31;
    const int warp = tid >> 5;
    const int wm   = warp >> 2;   // 0..1
    const int wn   = warp & 3;    // 0..3
    const int bm0  = blockIdx.y * BM;
    const int bn0  = blockIdx.x * BN;
    const int kz   = blockIdx.z;
    const int kt0  = kz * NT_ITERS;

    if (tid == 0) {
#pragma unroll
        for (int s = 0; s < STAGES; ++s) {
            mbar_init(smem_base + FULL_OFF(s),  NTHREADS);
            mbar_init(smem_base + EMPTY_OFF(s), 8);
        }
    }
    __syncthreads();

    const int prow = tid >> 3, pch = tid & 7;
    const uint32_t dst0 = (uint32_t)(prow * 128 + ((pch ^ (prow & 7)) << 4));
    const __half* pA = g_A  + (size_t)(bm0 + prow) * K_DIM + pch * 8 + (size_t)kt0 * BK;
    const __half* pB = g_Wt + (size_t)(bn0 + prow) * K_DIM + pch * 8 + (size_t)kt0 * BK;

    float c[4][4][4];
#pragma unroll
    for (int i = 0; i < 4; ++i)
#pragma unroll
        for (int j = 0; j < 4; ++j)
#pragma unroll
            for (int k = 0; k < 4; ++k) c[i][j][k] = 0.f;

#pragma unroll
    for (int s = 0; s < STAGES - 1; ++s) {
        issue_stage(smem_base + s * STAGE_BYTES, pA, pB, dst0);
        cpasync_arrive_noinc(smem_base + FULL_OFF(s));
        pA += BK; pB += BK;
    }

    int prod_s = STAGES - 1; uint32_t prod_ph = 1;
    int cons_s = 0;          uint32_t cons_ph = 0;

    for (int kt = 0; kt < NT_ITERS; ++kt) {
        wait_parity(smem_base + FULL_OFF(cons_s), cons_ph);
        const uint32_t st = smem_base + cons_s * STAGE_BYTES;

        uint32_t a[4][4], b[4][2];
        load_frags(st, 0, wm, wn, lane, a, b);

        if (kt + STAGES - 1 < NT_ITERS) {
            wait_parity(smem_base + EMPTY_OFF(prod_s), prod_ph);
            issue_stage(smem_base + prod_s * STAGE_BYTES, pA, pB, dst0);
            cpasync_arrive_noinc(smem_base + FULL_OFF(prod_s));
            pA += BK; pB += BK;
            if (++prod_s == STAGES) { prod_s = 0; prod_ph ^= 1; }
        }

#pragma unroll
        for (int mt = 0; mt < 4; ++mt)
#pragma unroll
            for (int nt = 0; nt < 4; ++nt)
                mma_f16(c[mt][nt], a[mt], b[nt]);

#pragma unroll
        for (int s = 1; s < 4; ++s) {
            load_frags(st, s, wm, wn, lane, a, b);
#pragma unroll
            for (int mt = 0; mt < 4; ++mt)
#pragma unroll
                for (int nt = 0; nt < 4; ++nt)
                    mma_f16(c[mt][nt], a[mt], b[nt]);
        }

        if (lane == 0) mbar_arrive(smem_base + EMPTY_OFF(cons_s));
        if (++cons_s == STAGES) { cons_s = 0; cons_ph ^= 1; }
    }

    // epilogue: vectorized reductions
    const int gr = lane >> 2;
    const int ct = lane & 3;
#pragma unroll
    for (int mt = 0; mt < 4; ++mt) {
#pragma unroll
        for (int nt = 0; nt < 4; ++nt) {
            int row = bm0 + wm * 64 + mt * 16 + gr;
            int o   = bn0 + wn * 32 + nt * 8 + ct * 2;
            float* p0 = out + (size_t)row * N_DIM + o;
            red_add_v2(p0, c[mt][nt][0], c[mt][nt][1]);
            red_add_v2(p0 + (size_t)8 * N_DIM, c[mt][nt][2], c[mt][nt][3]);
        }
    }

    // fused ReLU: 8th arriver on this output tile applies ReLU in place
    __threadfence();   // release our reductions
    if (tid == 0) {
        int tile = blockIdx.y * (N_DIM / BN) + blockIdx.x;
        int old = atomicAdd(&g_cnt[tile], 1);
        *reinterpret_cast<int*>(smem_raw + FLAG_OFF) = (old == KCHUNKS - 1);
    }
    __syncthreads();
    if (*reinterpret_cast<int*>(smem_raw + FLAG_OFF)) {
        __threadfence();   // acquire all chunks' reductions
        // 128x128 tile = 4096 float4; 16 per thread
#pragma unroll
        for (int k = 0; k < 16; ++k) {
            int idx = tid + k * NTHREADS;
            int row = idx >> 5;
            int col = (idx & 31) * 4;
            float* p = out + (size_t)(bm0 + row) * N_DIM + bn0 + col;
            float4 v = *reinterpret_cast<float4*>(p);
            v.x = fmaxf(v.x, 0.f); v.y = fmaxf(v.y, 0.f);
            v.z = fmaxf(v.z, 0.f); v.w = fmaxf(v.w, 0.f);
            *reinterpret_cast<float4*>(p) = v;
        }
    }
}

// ---------------- launch -----------------------------------------------------
extern "C" void kernel_launch(void* const* d_in, const int* in_sizes, int n_in,
                              void* d_out, int out_size) {
    const float* x = nullptr;
    const float* cw = nullptr;
    const float* W = nullptr;
    const float* bias = nullptr;
    for (int i = 0; i < n_in; ++i) {
        switch (in_sizes[i]) {
            case M_DIM * I_DIM:         x    = (const float*)d_in[i]; break;
            case M_DIM * E_DIM:         cw   = (const float*)d_in[i]; break;
            case E_DIM * I_DIM * N_DIM: W    = (const float*)d_in[i]; break;
            case E_DIM * N_DIM:         bias = (const float*)d_in[i]; break;
            default: break;
        }
    }
    float* out = (float*)d_out;

    init_out_kernel<<<(M_DIM * N_DIM / 4 + 255) / 256, 256>>>(out, cw, bias);
    prep_w_kernel<<<dim3(K_DIM / 32, N_DIM / 32), dim3(32, 8)>>>(W);
    prep_a_kernel<<<4096, 256>>>(x, cw);

    cudaFuncSetAttribute(gemm_kernel, cudaFuncAttributeMaxDynamicSharedMemorySize,
                         SMEM_TOTAL);
    dim3 grid(N_DIM / BN, M_DIM / BM, KCHUNKS);  // (8, 32, 8) = 2048 CTAs
    gemm_kernel<<<grid, NTHREADS, SMEM_TOTAL>>>(out);
}